// round 13
// baseline (speedup 1.0000x reference)
#include <cuda_runtime.h>
#include <cuda_fp16.h>
#include <cstdint>

// ---------------------------------------------------------------------------
// OuterProductMean: S=256, N=256, c_m=256, c_h=32, c_z=128
//   k_lnproj : LN + dual projection -> A, B plain fp16, K-major [m=8192][s=256]
//   k_wprep  : w_out fp32 [1024][128] -> plain fp16 transposed [z=128][k=1024]
//   k_norm   : g_rnorm[i,j] = 1/(sum_s mask[s,i]mask[s,j] + 1e-3)
//   k_gemm1  : HMMA 1-pass  C[8192x8192] = A B^T (K=256), C plain fp16
//   k_gemm2  : HMMA 1-pass  out = C W + bias, * rnorm; i DESCENDING so the
//              C rows gemm1 wrote last (still L2-resident, ~126MB) are read
//              first -> ~half of C reads become L2 hits.
// fp16 error model (validated R12): 4 sources ~2.1e-4 each -> 4.2e-4 total.
// All PTX sm_80-compatible (mma.sync/ldmatrix/cp.async) -> ok for compute_100.
// ---------------------------------------------------------------------------

#define S_DIM 256
#define N_DIM 256
#define CM    256
#define CH    32
#define CZ    128
#define NH    8192

__device__ __align__(16) __half g_A [(size_t)NH * S_DIM];
__device__ __align__(16) __half g_B [(size_t)NH * S_DIM];
__device__ __align__(16) __half g_C [(size_t)NH * NH];     // 134 MB
__device__ __align__(16) __half g_W [CZ * 1024];
__device__ __align__(16) float g_rnorm[N_DIM * N_DIM];

// ---- PTX helpers -----------------------------------------------------------
__device__ __forceinline__ uint32_t smem_u32(const void* p) {
    uint32_t a;
    asm("{ .reg .u64 t; cvta.to.shared.u64 t, %1; cvt.u32.u64 %0, t; }" : "=r"(a) : "l"(p));
    return a;
}
__device__ __forceinline__ void cp16(uint32_t dst, const void* src) {
    asm volatile("cp.async.cg.shared.global [%0], [%1], 16;" :: "r"(dst), "l"(src));
}
#define CP_COMMIT() asm volatile("cp.async.commit_group;" ::: "memory")
#define CP_WAIT(n)  asm volatile("cp.async.wait_group %0;" :: "n"(n) : "memory")

__device__ __forceinline__ void ldm4(uint32_t* r, uint32_t addr) {
    asm volatile("ldmatrix.sync.aligned.m8n8.x4.shared.b16 {%0,%1,%2,%3}, [%4];"
                 : "=r"(r[0]), "=r"(r[1]), "=r"(r[2]), "=r"(r[3]) : "r"(addr));
}
__device__ __forceinline__ void mma_fp16(float* c, const uint32_t* a, const uint32_t* b) {
    asm volatile(
        "mma.sync.aligned.m16n8k16.row.col.f32.f16.f16.f32 "
        "{%0,%1,%2,%3}, {%4,%5,%6,%7}, {%8,%9}, {%0,%1,%2,%3};"
        : "+f"(c[0]), "+f"(c[1]), "+f"(c[2]), "+f"(c[3])
        : "r"(a[0]), "r"(a[1]), "r"(a[2]), "r"(a[3]), "r"(b[0]), "r"(b[1]));
}

// smem tile geometry (both GEMMs): 128 rows x 64 halfs (128 B) + 16 B pad
#define ROW_B   144
#define ARR_SZ  (128 * ROW_B)        // 18432
#define STG_SZ  (2 * ARR_SZ)         // 36864 per stage (2 arrays)
#define OFF_0   0
#define OFF_1   ARR_SZ
#define NSTG    3
#define SMEM_GEMM (NSTG * STG_SZ)    // 110592 -> 2 CTAs/SM

// ---------------------------------------------------------------------------
__global__ __launch_bounds__(256) void k_norm(const float* __restrict__ mask) {
    const int i = blockIdx.x;
    const int j = threadIdx.x;
    __shared__ float colI[S_DIM];
    colI[j] = mask[j * N_DIM + i];
    __syncthreads();
    float acc = 0.0f;
#pragma unroll 8
    for (int s = 0; s < S_DIM; s++) acc += colI[s] * mask[s * N_DIM + j];
    g_rnorm[i * N_DIM + j] = 1.0f / (acc + 1e-3f);
}

__global__ __launch_bounds__(256) void k_wprep(const float* __restrict__ wout) {
    const int z = blockIdx.x;
    for (int k = threadIdx.x; k < 1024; k += 256)
        g_W[z * 1024 + k] = __float2half(wout[(size_t)k * CZ + z]);
}

// ---------------------------------------------------------------------------
// LN + dual projection, batched phases; psum overlays dead xs region (32 KB).
// grid = (n=256, sg=8); 256 threads; rows s = sg*32..+32 at fixed n.
// ---------------------------------------------------------------------------
__global__ __launch_bounds__(256) void k_lnproj(
    const float* __restrict__ m, const float* __restrict__ mask,
    const float* __restrict__ lnw, const float* __restrict__ lnb,
    const float* __restrict__ w1, const float* __restrict__ b1,
    const float* __restrict__ w2, const float* __restrict__ b2)
{
    const int tid  = threadIdx.x;
    const int lane = tid & 31;
    const int wid  = tid >> 5;
    const int n    = blockIdx.x;
    const int sg   = blockIdx.y;

    __shared__ float xs[32 * 256];          // phase A-D: rows; phase E: psum
    __shared__ float mu_s[32], inv_s[32];

    const int c = tid & 63;
    const int g = tid >> 6;
    float4 wreg[16];
#pragma unroll
    for (int k4 = 0; k4 < 16; k4++) {
        const int k = g * 64 + k4 * 4;
        if (c < CH) {
            wreg[k4] = make_float4(w1[k * CH + c], w1[(k + 1) * CH + c],
                                   w1[(k + 2) * CH + c], w1[(k + 3) * CH + c]);
        } else {
            const int cc = c - CH;
            wreg[k4] = make_float4(w2[k * CH + cc], w2[(k + 1) * CH + cc],
                                   w2[(k + 2) * CH + cc], w2[(k + 3) * CH + cc]);
        }
    }
    const float wln = lnw[tid];
    const float bln = lnb[tid];

    // Phase A: load 32 rows (coalesced float4)
#pragma unroll
    for (int l = 0; l < 8; l++) {
        const int idx = tid + 256 * l;
        const int r   = idx >> 6;
        const int c4  = idx & 63;
        const size_t row = (size_t)((sg * 32 + r) * N_DIM + n);
        ((float4*)xs)[r * 64 + c4] = ((const float4*)(m + row * CM))[c4];
    }
    __syncthreads();

    // Phase B: stats, warp w handles rows 4w..4w+3
#pragma unroll
    for (int rr = 0; rr < 4; rr++) {
        const int r = wid * 4 + rr;
        float s1 = 0.f, s2 = 0.f;
#pragma unroll
        for (int q = 0; q < 8; q++) {
            const float x = xs[r * 256 + lane + 32 * q];
            s1 += x; s2 += x * x;
        }
#pragma unroll
        for (int off = 16; off; off >>= 1) {
            s1 += __shfl_xor_sync(0xffffffffu, s1, off);
            s2 += __shfl_xor_sync(0xffffffffu, s2, off);
        }
        if (lane == 0) {
            const float mean = s1 * (1.0f / CM);
            const float var  = s2 * (1.0f / CM) - mean * mean;
            mu_s[r]  = mean;
            inv_s[r] = rsqrtf(var + 1e-5f);
        }
    }
    __syncthreads();

    // Phase C: normalize column tid across all rows (in place)
#pragma unroll 4
    for (int r = 0; r < 32; r++) {
        const float x = xs[r * 256 + tid];
        xs[r * 256 + tid] = (x - mu_s[r]) * inv_s[r] * wln + bln;
    }
    __syncthreads();

    // Phase D: projection partials kept in registers
    float pr[32];
#pragma unroll 2
    for (int r = 0; r < 32; r++) {
        const float4* yp = (const float4*)&xs[r * 256 + g * 64];
        float p = 0.f;
#pragma unroll
        for (int k4 = 0; k4 < 16; k4++) {
            const float4 y = yp[k4];
            const float4 w = wreg[k4];
            p += y.x * w.x + y.y * w.y + y.z * w.z + y.w * w.w;
        }
        pr[r] = p;
    }
    __syncthreads();     // xs reads done -> safe to overwrite with psum

#pragma unroll
    for (int rr = 0; rr < 32; rr++) {
        const int r = (lane + rr) & 31;
        xs[(g * 64 + c) * 32 + r] = pr[r];
    }
    __syncthreads();

    // Phase E: reduce over g, bias, mask, plain fp16 emit
    const int r = tid & 31;
    const size_t row = (size_t)((sg * 32 + r) * N_DIM + n);
    const float msk = mask[row];
#pragma unroll
    for (int l = 0; l < 8; l++) {
        const int cc = (tid >> 5) + 8 * l;      // 0..63
        const float tot = xs[(0 * 64 + cc) * 32 + r] + xs[(1 * 64 + cc) * 32 + r] +
                          xs[(2 * 64 + cc) * 32 + r] + xs[(3 * 64 + cc) * 32 + r];
        const float bias = (cc < CH) ? b1[cc] : b2[cc - CH];
        const float v = (tot + bias) * msk;
        if (cc < CH) {
            const size_t mrow = (size_t)(n * CH + cc) * S_DIM + sg * 32 + r;
            g_A[mrow] = __float2half(v);
        } else {
            const size_t mrow = (size_t)(n * CH + (cc - CH)) * S_DIM + sg * 32 + r;
            g_B[mrow] = __float2half(v);
        }
    }
}

// ---------------------------------------------------------------------------
// K2: C = A B^T, 1-pass HMMA. CTA tile 128x128, K=256 in 4 chunks of 64,
// 3-stage ring. 8 warps as 4(m) x 2(n); warp tile 32(m) x 64(n).
// ---------------------------------------------------------------------------
__global__ __launch_bounds__(256, 2) void k_gemm1() {
    extern __shared__ char smraw[];
    const uint32_t sm0 = smem_u32(smraw);
    const int tid  = threadIdx.x;
    const int wid  = tid >> 5;
    const int lane = tid & 31;
    const int m0 = blockIdx.y * 128;
    const int n0 = blockIdx.x * 128;
    const int wm0 = (wid & 3) * 32;
    const int wn0 = (wid >> 2) * 64;

    const int ar = lane & 15;
    const int ak = (lane >> 4) * 16;
    const int br = (lane & 7) + ((lane >> 4) << 3);
    const int bk = ((lane >> 3) & 1) * 16;
    const uint32_t aoff = (uint32_t)(wm0 + ar) * ROW_B + ak;
    const uint32_t boff = (uint32_t)(wn0 + br) * ROW_B + bk;

    float acc[2][8][4];
#pragma unroll
    for (int t = 0; t < 2; t++)
#pragma unroll
        for (int j = 0; j < 8; j++)
#pragma unroll
            for (int q = 0; q < 4; q++) acc[t][j][q] = 0.f;

    auto stage = [&](int kc, uint32_t sbuf) {
#pragma unroll
        for (int l = 0; l < 4; l++) {
            const int idx = tid + 256 * l;      // 1024: row(128) x seg(8)
            const int row = idx >> 3;
            const int seg = idx & 7;
            const uint32_t d = sbuf + row * ROW_B + seg * 16;
            const size_t sa = (size_t)(m0 + row) * S_DIM + kc * 64 + seg * 8;
            const size_t sb = (size_t)(n0 + row) * S_DIM + kc * 64 + seg * 8;
            cp16(d + OFF_0, g_A + sa);
            cp16(d + OFF_1, g_B + sb);
        }
        CP_COMMIT();
    };

    stage(0, sm0);
    stage(1, sm0 + STG_SZ);
    stage(2, sm0 + 2 * STG_SZ);

#pragma unroll
    for (int kc = 0; kc < 4; kc++) {
        if (kc <= 1)      { CP_WAIT(2); }
        else if (kc == 2) { CP_WAIT(1); }
        else              { CP_WAIT(0); }
        __syncthreads();
        const uint32_t sbuf = sm0 + (kc % 3) * STG_SZ;
#pragma unroll
        for (int ks = 0; ks < 4; ks++) {
            uint32_t a[2][4], b[4][4];
#pragma unroll
            for (int t = 0; t < 2; t++)
                ldm4(a[t], sbuf + aoff + t * (16 * ROW_B) + ks * 32 + OFF_0);
#pragma unroll
            for (int p = 0; p < 4; p++)
                ldm4(b[p], sbuf + boff + p * (16 * ROW_B) + ks * 32 + OFF_1);
#pragma unroll
            for (int t = 0; t < 2; t++) {
#pragma unroll
                for (int j = 0; j < 8; j++)
                    mma_fp16(acc[t][j], a[t], &b[j >> 1][(j & 1) * 2]);
            }
        }
        __syncthreads();
        if (kc + 3 < 4) stage(kc + 3, sbuf);
    }

    // epilogue: plain fp16 C, packed u32 stores (row-major)
#pragma unroll
    for (int t = 0; t < 2; t++) {
        const int mg = m0 + wm0 + t * 16 + (lane >> 2);
#pragma unroll
        for (int j = 0; j < 8; j++) {
            const int nn = n0 + wn0 + j * 8 + (lane & 3) * 2;
            const float* cc = acc[t][j];
#pragma unroll
            for (int h = 0; h < 2; h++) {
                __half2 hp;
                hp.x = __float2half(cc[h * 2 + 0]);
                hp.y = __float2half(cc[h * 2 + 1]);
                const size_t o = (size_t)(mg + h * 8) * NH + nn;
                *(uint32_t*)(g_C + o) = *(uint32_t*)&hp;
            }
        }
    }
}

// ---------------------------------------------------------------------------
// K3: out[(i,j),z] = (sum_ce C[(i,c),(j,e)] W[ce,z] + b[z]) * rnorm[i,j]
// grid = 512, i DESCENDING (i = 255 - bx>>1): gemm1's last-written C rows
// (high m = high i, still L2-resident) are consumed first.
// CTA tile 128(j) x 128(z), K=1024 in 16 chunks of 64, 3-stage ring.
// ---------------------------------------------------------------------------
__global__ __launch_bounds__(256, 2) void k_gemm2(
    const float* __restrict__ bout, float* __restrict__ out)
{
    extern __shared__ char smraw[];
    const uint32_t sm0 = smem_u32(smraw);
    const int tid  = threadIdx.x;
    const int wid  = tid >> 5;
    const int lane = tid & 31;
    const int i  = 255 - (blockIdx.x >> 1);   // descending i for L2 reuse of C
    const int jh = blockIdx.x & 1;
    const int wm0 = (wid & 3) * 32;      // j within tile
    const int wn0 = (wid >> 2) * 64;     // z

    const int ar = lane & 15;
    const int ak = (lane >> 4) * 16;
    const int br = (lane & 7) + ((lane >> 4) << 3);
    const int bk = ((lane >> 3) & 1) * 16;
    const uint32_t aoff = (uint32_t)(wm0 + ar) * ROW_B + ak;
    const uint32_t boff = (uint32_t)(wn0 + br) * ROW_B + bk;

    float acc[2][8][4];
#pragma unroll
    for (int t = 0; t < 2; t++)
#pragma unroll
        for (int j = 0; j < 8; j++)
#pragma unroll
            for (int q = 0; q < 4; q++) acc[t][j][q] = 0.f;

    auto stage = [&](int kc, uint32_t sbuf) {
#pragma unroll
        for (int l = 0; l < 4; l++) {
            const int idx = tid + 256 * l;
            const int row = idx >> 3;            // j-row (C) / z-row (W)
            const int seg = idx & 7;             // k-halfs seg*8..+8
            const uint32_t d = sbuf + row * ROW_B + seg * 16;
            // C source: c = kc*2 + (seg>>2), e = (seg&3)*8
            const size_t sc = (size_t)(i * 32 + kc * 2 + (seg >> 2)) * NH +
                              (size_t)(jh * 128 + row) * 32 + (seg & 3) * 8;
            const size_t sw = (size_t)row * 1024 + kc * 64 + seg * 8;
            cp16(d + OFF_0, g_C + sc);
            cp16(d + OFF_1, g_W + sw);
        }
        CP_COMMIT();
    };

    stage(0, sm0);
    stage(1, sm0 + STG_SZ);
    stage(2, sm0 + 2 * STG_SZ);

    for (int kc = 0; kc < 16; kc++) {
        if (kc < 14)       { CP_WAIT(2); }
        else if (kc == 14) { CP_WAIT(1); }
        else               { CP_WAIT(0); }
        __syncthreads();
        const uint32_t sbuf = sm0 + (kc % 3) * STG_SZ;
#pragma unroll
        for (int ks = 0; ks < 4; ks++) {
            uint32_t a[2][4], b[4][4];
#pragma unroll
            for (int t = 0; t < 2; t++)
                ldm4(a[t], sbuf + aoff + t * (16 * ROW_B) + ks * 32 + OFF_0);
#pragma unroll
            for (int p = 0; p < 4; p++)
                ldm4(b[p], sbuf + boff + p * (16 * ROW_B) + ks * 32 + OFF_1);
#pragma unroll
            for (int t = 0; t < 2; t++) {
#pragma unroll
                for (int j = 0; j < 8; j++)
                    mma_fp16(acc[t][j], a[t], &b[j >> 1][(j & 1) * 2]);
            }
        }
        __syncthreads();
        if (kc + 3 < 16) stage(kc + 3, sbuf);
    }

    // epilogue: + bias, * rnorm, fp32 stores
#pragma unroll
    for (int t = 0; t < 2; t++) {
        const int jg = jh * 128 + wm0 + t * 16 + (lane >> 2);
        const float rn0 = g_rnorm[i * N_DIM + jg];
        const float rn1 = g_rnorm[i * N_DIM + jg + 8];
#pragma unroll
        for (int j = 0; j < 8; j++) {
            const int z = wn0 + j * 8 + (lane & 3) * 2;
            const float2 bz = *(const float2*)(bout + z);
            const float* cc = acc[t][j];
            float2 o0, o1;
            o0.x = (cc[0] + bz.x) * rn0;  o0.y = (cc[1] + bz.y) * rn0;
            o1.x = (cc[2] + bz.x) * rn1;  o1.y = (cc[3] + bz.y) * rn1;
            *(float2*)(out + (size_t)(i * N_DIM + jg) * CZ + z)     = o0;
            *(float2*)(out + (size_t)(i * N_DIM + jg + 8) * CZ + z) = o1;
        }
    }
}

// ---------------------------------------------------------------------------
extern "C" void kernel_launch(void* const* d_in, const int* in_sizes, int n_in,
                              void* d_out, int out_size)
{
    (void)in_sizes; (void)n_in; (void)out_size;
    const float* m    = (const float*)d_in[0];
    const float* mask = (const float*)d_in[1];
    const float* lnw  = (const float*)d_in[2];
    const float* lnb  = (const float*)d_in[3];
    const float* w1   = (const float*)d_in[4];
    const float* b1   = (const float*)d_in[5];
    const float* w2   = (const float*)d_in[6];
    const float* b2   = (const float*)d_in[7];
    const float* wout = (const float*)d_in[8];
    const float* bout = (const float*)d_in[9];
    float* out = (float*)d_out;

    cudaFuncSetAttribute((const void*)k_gemm1,
                         cudaFuncAttributeMaxDynamicSharedMemorySize, SMEM_GEMM);
    cudaFuncSetAttribute((const void*)k_gemm2,
                         cudaFuncAttributeMaxDynamicSharedMemorySize, SMEM_GEMM);

    k_lnproj<<<dim3(N_DIM, 8), 256>>>(m, mask, lnw, lnb, w1, b1, w2, b2);
    k_wprep<<<CZ, 256>>>(wout);
    k_norm<<<N_DIM, 256>>>(mask);
    k_gemm1<<<dim3(NH / 128, NH / 128), 256, SMEM_GEMM>>>();
    k_gemm2<<<512, 256, SMEM_GEMM>>>(bout, out);
}

// round 14
// speedup vs baseline: 1.2088x; 1.2088x over previous
#include <cuda_runtime.h>
#include <cuda_fp16.h>
#include <cstdint>

// ---------------------------------------------------------------------------
// OuterProductMean: S=256, N=256, c_m=256, c_h=32, c_z=128
//   k_lnproj : LN (fp32) + HMMA projection (fp16) -> A,B fp16 K-major [m][s]
//   k_prep   : merged  rnorm (blocks 0-255)  +  W transpose fp16 (256-383)
//   k_gemm1  : HMMA 1-pass  C[8192x8192] = A B^T (K=256), C plain fp16
//   k_gemm2  : HMMA 1-pass  out = C W + bias, * rnorm
// fp16 error model: 5 quantization sources (~2.1e-4 each) -> ~4.6e-4 total.
// All PTX sm_80-compatible (mma.sync/ldmatrix/cp.async) -> ok for compute_100.
// ---------------------------------------------------------------------------

#define S_DIM 256
#define N_DIM 256
#define CM    256
#define CH    32
#define CZ    128
#define NH    8192

__device__ __align__(16) __half g_A [(size_t)NH * S_DIM];
__device__ __align__(16) __half g_B [(size_t)NH * S_DIM];
__device__ __align__(16) __half g_C [(size_t)NH * NH];     // 134 MB
__device__ __align__(16) __half g_W [CZ * 1024];
__device__ __align__(16) float g_rnorm[N_DIM * N_DIM];

// ---- PTX helpers -----------------------------------------------------------
__device__ __forceinline__ uint32_t smem_u32(const void* p) {
    uint32_t a;
    asm("{ .reg .u64 t; cvta.to.shared.u64 t, %1; cvt.u32.u64 %0, t; }" : "=r"(a) : "l"(p));
    return a;
}
__device__ __forceinline__ void cp16(uint32_t dst, const void* src) {
    asm volatile("cp.async.cg.shared.global [%0], [%1], 16;" :: "r"(dst), "l"(src));
}
#define CP_COMMIT() asm volatile("cp.async.commit_group;" ::: "memory")
#define CP_WAIT(n)  asm volatile("cp.async.wait_group %0;" :: "n"(n) : "memory")

__device__ __forceinline__ void ldm4(uint32_t* r, uint32_t addr) {
    asm volatile("ldmatrix.sync.aligned.m8n8.x4.shared.b16 {%0,%1,%2,%3}, [%4];"
                 : "=r"(r[0]), "=r"(r[1]), "=r"(r[2]), "=r"(r[3]) : "r"(addr));
}
__device__ __forceinline__ void ldm4t(uint32_t* r, uint32_t addr) {
    asm volatile("ldmatrix.sync.aligned.m8n8.x4.trans.shared.b16 {%0,%1,%2,%3}, [%4];"
                 : "=r"(r[0]), "=r"(r[1]), "=r"(r[2]), "=r"(r[3]) : "r"(addr));
}
__device__ __forceinline__ void mma_fp16(float* c, const uint32_t* a, const uint32_t* b) {
    asm volatile(
        "mma.sync.aligned.m16n8k16.row.col.f32.f16.f16.f32 "
        "{%0,%1,%2,%3}, {%4,%5,%6,%7}, {%8,%9}, {%0,%1,%2,%3};"
        : "+f"(c[0]), "+f"(c[1]), "+f"(c[2]), "+f"(c[3])
        : "r"(a[0]), "r"(a[1]), "r"(a[2]), "r"(a[3]), "r"(b[0]), "r"(b[1]));
}

// smem tile geometry (both GEMMs): 128 rows x 64 halfs (128 B) + 16 B pad
#define ROW_B   144
#define ARR_SZ  (128 * ROW_B)        // 18432
#define STG_SZ  (2 * ARR_SZ)         // 36864 per stage (2 arrays)
#define OFF_0   0
#define OFF_1   ARR_SZ
#define NSTG    3
#define SMEM_GEMM (NSTG * STG_SZ)    // 110592 -> 2 CTAs/SM

// lnproj dynamic smem layout (bytes)
#define LP_YS    0                   // ysm: 32 rows x 264 halfs (528 B)
#define LP_W     16896               // Wsm: 256 k-rows x 72 halfs (144 B)
#define LP_XS    (16896 + 36864)     // xs fp32 32x256 (32 KB); tbuf overlays
#define LP_SMEM  (LP_XS + 32768)     // 86528

// ---------------------------------------------------------------------------
// merged prep: blocks 0-255 -> rnorm row i; blocks 256-383 -> W transpose z
// ---------------------------------------------------------------------------
__global__ __launch_bounds__(256) void k_prep(const float* __restrict__ mask,
                                              const float* __restrict__ wout) {
    if (blockIdx.x < 256) {
        const int i = blockIdx.x;
        const int j = threadIdx.x;
        __shared__ float colI[S_DIM];
        colI[j] = mask[j * N_DIM + i];
        __syncthreads();
        float acc = 0.0f;
#pragma unroll 8
        for (int s = 0; s < S_DIM; s++) acc += colI[s] * mask[s * N_DIM + j];
        g_rnorm[i * N_DIM + j] = 1.0f / (acc + 1e-3f);
    } else {
        const int z = blockIdx.x - 256;
        for (int k = threadIdx.x; k < 1024; k += 256)
            g_W[z * 1024 + k] = __float2half(wout[(size_t)k * CZ + z]);
    }
}

// ---------------------------------------------------------------------------
// LN + HMMA dual projection.
// grid = (n=256, sg=8); 256 thr; rows s = sg*32..+32 at fixed n; 8 warps.
// Warp w computes output cols cc = w*8..w*8+8 over all 32 rows via mma.
// ---------------------------------------------------------------------------
__global__ __launch_bounds__(256) void k_lnproj(
    const float* __restrict__ m, const float* __restrict__ mask,
    const float* __restrict__ lnw, const float* __restrict__ lnb,
    const float* __restrict__ w1, const float* __restrict__ b1,
    const float* __restrict__ w2, const float* __restrict__ b2)
{
    extern __shared__ char smraw[];
    __half* ys   = (__half*)(smraw + LP_YS);     // [r][264]
    __half* Wsm  = (__half*)(smraw + LP_W);      // [k][72]
    float*  xs   = (float*)(smraw + LP_XS);      // [r][256]
    __half* tbuf = (__half*)(smraw + LP_XS);     // overlay: [cc][40]
    __shared__ float mu_s[32], inv_s[32], msm[32];

    const uint32_t ys_b  = smem_u32(ys);
    const uint32_t W_b   = smem_u32(Wsm);
    const int tid  = threadIdx.x;
    const int lane = tid & 31;
    const int wid  = tid >> 5;
    const int n    = blockIdx.x;
    const int sg   = blockIdx.y;

    const float wln = lnw[tid];
    const float bln = lnb[tid];

    // Phase A: load 32 rows of m (coalesced float4) + W smem + mask
#pragma unroll
    for (int l = 0; l < 8; l++) {
        const int idx = tid + 256 * l;
        const int r   = idx >> 6;
        const int c4  = idx & 63;
        const size_t row = (size_t)((sg * 32 + r) * N_DIM + n);
        ((float4*)xs)[r * 64 + c4] = ((const float4*)(m + row * CM))[c4];
    }
    for (int idx = tid; idx < 256 * 64; idx += 256) {
        const int k = idx >> 6;
        const int c = idx & 63;
        const float v = (c < CH) ? w1[k * CH + c] : w2[k * CH + (c - CH)];
        Wsm[k * 72 + c] = __float2half(v);
    }
    if (tid < 32) msm[tid] = mask[(size_t)((sg * 32 + tid) * N_DIM + n)];
    __syncthreads();

    // Phase B: LN stats, warp w handles rows 4w..4w+3
#pragma unroll
    for (int rr = 0; rr < 4; rr++) {
        const int r = wid * 4 + rr;
        float s1 = 0.f, s2 = 0.f;
#pragma unroll
        for (int q = 0; q < 8; q++) {
            const float x = xs[r * 256 + lane + 32 * q];
            s1 += x; s2 += x * x;
        }
#pragma unroll
        for (int off = 16; off; off >>= 1) {
            s1 += __shfl_xor_sync(0xffffffffu, s1, off);
            s2 += __shfl_xor_sync(0xffffffffu, s2, off);
        }
        if (lane == 0) {
            const float mean = s1 * (1.0f / CM);
            const float var  = s2 * (1.0f / CM) - mean * mean;
            mu_s[r]  = mean;
            inv_s[r] = rsqrtf(var + 1e-5f);
        }
    }
    __syncthreads();

    // Phase C: normalize -> fp16 ysm
#pragma unroll 4
    for (int r = 0; r < 32; r++) {
        const float x = xs[r * 256 + tid];
        ys[r * 264 + tid] = __float2half((x - mu_s[r]) * inv_s[r] * wln + bln);
    }
    __syncthreads();

    // Phase D: HMMA projection. acc = 32 rows x 8 cols per warp.
    const int ar = lane & 15;
    const int ak = (lane >> 4) * 16;
    float acc[2][4];
#pragma unroll
    for (int t = 0; t < 2; t++)
#pragma unroll
        for (int q = 0; q < 4; q++) acc[t][q] = 0.f;

#pragma unroll
    for (int q2 = 0; q2 < 8; q2++) {               // k32 per iter
        uint32_t bf[4];
        ldm4t(bf, W_b + (uint32_t)(q2 * 32 + lane) * 144 + wid * 16);
#pragma unroll
        for (int s = 0; s < 2; s++) {              // kstep = 2*q2+s
            const int q = 2 * q2 + s;
            uint32_t af[2][4];
#pragma unroll
            for (int t = 0; t < 2; t++)
                ldm4(af[t], ys_b + (uint32_t)(t * 16 + ar) * 528 + q * 32 + ak);
            mma_fp16(acc[0], af[0], &bf[s * 2]);
            mma_fp16(acc[1], af[1], &bf[s * 2]);
        }
    }

    // Phase E: bias + mask -> tbuf[cc][r] fp16 (xs now dead)
    const int cc0 = wid * 8 + (lane & 3) * 2;
    const float bia0 = (cc0 < CH) ? b1[cc0] : b2[cc0 - CH];
    const float bia1 = (cc0 + 1 < CH) ? b1[cc0 + 1] : b2[cc0 + 1 - CH];
#pragma unroll
    for (int t = 0; t < 2; t++) {
#pragma unroll
        for (int q = 0; q < 4; q++) {
            const int r  = t * 16 + (lane >> 2) + (q >> 1) * 8;
            const int cc = cc0 + (q & 1);
            const float v = (acc[t][q] + ((q & 1) ? bia1 : bia0)) * msm[r];
            tbuf[cc * 40 + r] = __float2half(v);
        }
    }
    __syncthreads();

    // Phase F: coalesced K-major stores (64 B per output column)
    {
        const int cc  = tid >> 2;
        const int seg = tid & 3;
        uint4 v = *(const uint4*)(tbuf + cc * 40 + seg * 8);
        __half* dst = (cc < CH)
            ? (g_A + (size_t)(n * CH + cc) * S_DIM + sg * 32 + seg * 8)
            : (g_B + (size_t)(n * CH + (cc - CH)) * S_DIM + sg * 32 + seg * 8);
        *(uint4*)dst = v;
    }
}

// ---------------------------------------------------------------------------
// K2: C = A B^T, 1-pass HMMA. CTA tile 128x128, K=256 in 4 chunks of 64,
// 3-stage ring. 8 warps as 4(m) x 2(n); warp tile 32(m) x 64(n).
// ---------------------------------------------------------------------------
__global__ __launch_bounds__(256, 2) void k_gemm1() {
    extern __shared__ char smraw[];
    const uint32_t sm0 = smem_u32(smraw);
    const int tid  = threadIdx.x;
    const int wid  = tid >> 5;
    const int lane = tid & 31;
    const int m0 = blockIdx.y * 128;
    const int n0 = blockIdx.x * 128;
    const int wm0 = (wid & 3) * 32;
    const int wn0 = (wid >> 2) * 64;

    const int ar = lane & 15;
    const int ak = (lane >> 4) * 16;
    const int br = (lane & 7) + ((lane >> 4) << 3);
    const int bk = ((lane >> 3) & 1) * 16;
    const uint32_t aoff = (uint32_t)(wm0 + ar) * ROW_B + ak;
    const uint32_t boff = (uint32_t)(wn0 + br) * ROW_B + bk;

    float acc[2][8][4];
#pragma unroll
    for (int t = 0; t < 2; t++)
#pragma unroll
        for (int j = 0; j < 8; j++)
#pragma unroll
            for (int q = 0; q < 4; q++) acc[t][j][q] = 0.f;

    auto stage = [&](int kc, uint32_t sbuf) {
#pragma unroll
        for (int l = 0; l < 4; l++) {
            const int idx = tid + 256 * l;      // 1024: row(128) x seg(8)
            const int row = idx >> 3;
            const int seg = idx & 7;
            const uint32_t d = sbuf + row * ROW_B + seg * 16;
            const size_t sa = (size_t)(m0 + row) * S_DIM + kc * 64 + seg * 8;
            const size_t sb = (size_t)(n0 + row) * S_DIM + kc * 64 + seg * 8;
            cp16(d + OFF_0, g_A + sa);
            cp16(d + OFF_1, g_B + sb);
        }
        CP_COMMIT();
    };

    stage(0, sm0);
    stage(1, sm0 + STG_SZ);
    stage(2, sm0 + 2 * STG_SZ);

#pragma unroll
    for (int kc = 0; kc < 4; kc++) {
        if (kc <= 1)      { CP_WAIT(2); }
        else if (kc == 2) { CP_WAIT(1); }
        else              { CP_WAIT(0); }
        __syncthreads();
        const uint32_t sbuf = sm0 + (kc % 3) * STG_SZ;
#pragma unroll
        for (int ks = 0; ks < 4; ks++) {
            uint32_t a[2][4], b[4][4];
#pragma unroll
            for (int t = 0; t < 2; t++)
                ldm4(a[t], sbuf + aoff + t * (16 * ROW_B) + ks * 32 + OFF_0);
#pragma unroll
            for (int p = 0; p < 4; p++)
                ldm4(b[p], sbuf + boff + p * (16 * ROW_B) + ks * 32 + OFF_1);
#pragma unroll
            for (int t = 0; t < 2; t++) {
#pragma unroll
                for (int j = 0; j < 8; j++)
                    mma_fp16(acc[t][j], a[t], &b[j >> 1][(j & 1) * 2]);
            }
        }
        __syncthreads();
        if (kc + 3 < 4) stage(kc + 3, sbuf);
    }

    // epilogue: plain fp16 C, packed u32 stores (row-major)
#pragma unroll
    for (int t = 0; t < 2; t++) {
        const int mg = m0 + wm0 + t * 16 + (lane >> 2);
#pragma unroll
        for (int j = 0; j < 8; j++) {
            const int nn = n0 + wn0 + j * 8 + (lane & 3) * 2;
            const float* cc = acc[t][j];
#pragma unroll
            for (int h = 0; h < 2; h++) {
                __half2 hp;
                hp.x = __float2half(cc[h * 2 + 0]);
                hp.y = __float2half(cc[h * 2 + 1]);
                const size_t o = (size_t)(mg + h * 8) * NH + nn;
                *(uint32_t*)(g_C + o) = *(uint32_t*)&hp;
            }
        }
    }
}

// ---------------------------------------------------------------------------
// K3: out[(i,j),z] = (sum_ce C[(i,c),(j,e)] W[ce,z] + b[z]) * rnorm[i,j]
// grid = 512, i descending (L2-neutral but harmless). CTA tile 128(j) x
// 128(z), K=1024 in 16 chunks of 64, 3-stage ring.
// ---------------------------------------------------------------------------
__global__ __launch_bounds__(256, 2) void k_gemm2(
    const float* __restrict__ bout, float* __restrict__ out)
{
    extern __shared__ char smraw[];
    const uint32_t sm0 = smem_u32(smraw);
    const int tid  = threadIdx.x;
    const int wid  = tid >> 5;
    const int lane = tid & 31;
    const int i  = 255 - (blockIdx.x >> 1);
    const int jh = blockIdx.x & 1;
    const int wm0 = (wid & 3) * 32;      // j within tile
    const int wn0 = (wid >> 2) * 64;     // z

    const int ar = lane & 15;
    const int ak = (lane >> 4) * 16;
    const int br = (lane & 7) + ((lane >> 4) << 3);
    const int bk = ((lane >> 3) & 1) * 16;
    const uint32_t aoff = (uint32_t)(wm0 + ar) * ROW_B + ak;
    const uint32_t boff = (uint32_t)(wn0 + br) * ROW_B + bk;

    float acc[2][8][4];
#pragma unroll
    for (int t = 0; t < 2; t++)
#pragma unroll
        for (int j = 0; j < 8; j++)
#pragma unroll
            for (int q = 0; q < 4; q++) acc[t][j][q] = 0.f;

    auto stage = [&](int kc, uint32_t sbuf) {
#pragma unroll
        for (int l = 0; l < 4; l++) {
            const int idx = tid + 256 * l;
            const int row = idx >> 3;            // j-row (C) / z-row (W)
            const int seg = idx & 7;             // k-halfs seg*8..+8
            const uint32_t d = sbuf + row * ROW_B + seg * 16;
            const size_t sc = (size_t)(i * 32 + kc * 2 + (seg >> 2)) * NH +
                              (size_t)(jh * 128 + row) * 32 + (seg & 3) * 8;
            const size_t sw = (size_t)row * 1024 + kc * 64 + seg * 8;
            cp16(d + OFF_0, g_C + sc);
            cp16(d + OFF_1, g_W + sw);
        }
        CP_COMMIT();
    };

    stage(0, sm0);
    stage(1, sm0 + STG_SZ);
    stage(2, sm0 + 2 * STG_SZ);

    for (int kc = 0; kc < 16; kc++) {
        if (kc < 14)       { CP_WAIT(2); }
        else if (kc == 14) { CP_WAIT(1); }
        else               { CP_WAIT(0); }
        __syncthreads();
        const uint32_t sbuf = sm0 + (kc % 3) * STG_SZ;
#pragma unroll
        for (int ks = 0; ks < 4; ks++) {
            uint32_t a[2][4], b[4][4];
#pragma unroll
            for (int t = 0; t < 2; t++)
                ldm4(a[t], sbuf + aoff + t * (16 * ROW_B) + ks * 32 + OFF_0);
#pragma unroll
            for (int p = 0; p < 4; p++)
                ldm4(b[p], sbuf + boff + p * (16 * ROW_B) + ks * 32 + OFF_1);
#pragma unroll
            for (int t = 0; t < 2; t++) {
#pragma unroll
                for (int j = 0; j < 8; j++)
                    mma_fp16(acc[t][j], a[t], &b[j >> 1][(j & 1) * 2]);
            }
        }
        __syncthreads();
        if (kc + 3 < 16) stage(kc + 3, sbuf);
    }

    // epilogue: + bias, * rnorm, fp32 stores
#pragma unroll
    for (int t = 0; t < 2; t++) {
        const int jg = jh * 128 + wm0 + t * 16 + (lane >> 2);
        const float rn0 = g_rnorm[i * N_DIM + jg];
        const float rn1 = g_rnorm[i * N_DIM + jg + 8];
#pragma unroll
        for (int j = 0; j < 8; j++) {
            const int z = wn0 + j * 8 + (lane & 3) * 2;
            const float2 bz = *(const float2*)(bout + z);
            const float* cc = acc[t][j];
            float2 o0, o1;
            o0.x = (cc[0] + bz.x) * rn0;  o0.y = (cc[1] + bz.y) * rn0;
            o1.x = (cc[2] + bz.x) * rn1;  o1.y = (cc[3] + bz.y) * rn1;
            *(float2*)(out + (size_t)(i * N_DIM + jg) * CZ + z)     = o0;
            *(float2*)(out + (size_t)(i * N_DIM + jg + 8) * CZ + z) = o1;
        }
    }
}

// ---------------------------------------------------------------------------
extern "C" void kernel_launch(void* const* d_in, const int* in_sizes, int n_in,
                              void* d_out, int out_size)
{
    (void)in_sizes; (void)n_in; (void)out_size;
    const float* m    = (const float*)d_in[0];
    const float* mask = (const float*)d_in[1];
    const float* lnw  = (const float*)d_in[2];
    const float* lnb  = (const float*)d_in[3];
    const float* w1   = (const float*)d_in[4];
    const float* b1   = (const float*)d_in[5];
    const float* w2   = (const float*)d_in[6];
    const float* b2   = (const float*)d_in[7];
    const float* wout = (const float*)d_in[8];
    const float* bout = (const float*)d_in[9];
    float* out = (float*)d_out;

    cudaFuncSetAttribute((const void*)k_lnproj,
                         cudaFuncAttributeMaxDynamicSharedMemorySize, LP_SMEM);
    cudaFuncSetAttribute((const void*)k_gemm1,
                         cudaFuncAttributeMaxDynamicSharedMemorySize, SMEM_GEMM);
    cudaFuncSetAttribute((const void*)k_gemm2,
                         cudaFuncAttributeMaxDynamicSharedMemorySize, SMEM_GEMM);

    k_lnproj<<<dim3(N_DIM, 8), 256, LP_SMEM>>>(m, mask, lnw, lnb, w1, b1, w2, b2);
    k_prep<<<384, 256>>>(mask, wout);
    k_gemm1<<<dim3(NH / 128, NH / 128), 256, SMEM_GEMM>>>();
    k_gemm2<<<512, 256, SMEM_GEMM>>>(bout, out);
}

// round 15
// speedup vs baseline: 1.2990x; 1.0746x over previous
#include <cuda_runtime.h>
#include <cuda_fp16.h>
#include <cstdint>

// ---------------------------------------------------------------------------
// OuterProductMean: S=256, N=256, c_m=256, c_h=32, c_z=128
//   k_prep   : rnorm (blocks 0-255) + W transpose fp16 (256-383)
//              + proj-weight fp16 pack g_Wp (384-391).  Runs FIRST.
//   k_lnproj : LN (fp32) + HMMA projection (fp16) -> A,B fp16 K-major [m][s]
//   k_gemm1  : HMMA 1-pass  C[8192x8192] = A B^T (K=256); 128 thr, 64x64 warp
//   k_gemm2  : HMMA 1-pass  out = C W + bias, * rnorm;    128 thr, 64x64 warp
// 64x64 warp tiles halve smem bytes/FMA (8 LDSM.x4 per 32 mma) vs 32x64.
// fp16 error model (validated): ~5.9e-4 total, under 1e-3 gate.
// All PTX sm_80-compatible (mma.sync/ldmatrix/cp.async) -> ok for compute_100.
// ---------------------------------------------------------------------------

#define S_DIM 256
#define N_DIM 256
#define CM    256
#define CH    32
#define CZ    128
#define NH    8192

__device__ __align__(16) __half g_A [(size_t)NH * S_DIM];
__device__ __align__(16) __half g_B [(size_t)NH * S_DIM];
__device__ __align__(16) __half g_C [(size_t)NH * NH];     // 134 MB
__device__ __align__(16) __half g_W [CZ * 1024];
__device__ __align__(16) __half g_Wp[CM * 64];             // proj weights fp16
__device__ __align__(16) float g_rnorm[N_DIM * N_DIM];

// ---- PTX helpers -----------------------------------------------------------
__device__ __forceinline__ uint32_t smem_u32(const void* p) {
    uint32_t a;
    asm("{ .reg .u64 t; cvta.to.shared.u64 t, %1; cvt.u32.u64 %0, t; }" : "=r"(a) : "l"(p));
    return a;
}
__device__ __forceinline__ void cp16(uint32_t dst, const void* src) {
    asm volatile("cp.async.cg.shared.global [%0], [%1], 16;" :: "r"(dst), "l"(src));
}
#define CP_COMMIT() asm volatile("cp.async.commit_group;" ::: "memory")
#define CP_WAIT(n)  asm volatile("cp.async.wait_group %0;" :: "n"(n) : "memory")

__device__ __forceinline__ void ldm4(uint32_t* r, uint32_t addr) {
    asm volatile("ldmatrix.sync.aligned.m8n8.x4.shared.b16 {%0,%1,%2,%3}, [%4];"
                 : "=r"(r[0]), "=r"(r[1]), "=r"(r[2]), "=r"(r[3]) : "r"(addr));
}
__device__ __forceinline__ void ldm4t(uint32_t* r, uint32_t addr) {
    asm volatile("ldmatrix.sync.aligned.m8n8.x4.trans.shared.b16 {%0,%1,%2,%3}, [%4];"
                 : "=r"(r[0]), "=r"(r[1]), "=r"(r[2]), "=r"(r[3]) : "r"(addr));
}
__device__ __forceinline__ void mma_fp16(float* c, const uint32_t* a, const uint32_t* b) {
    asm volatile(
        "mma.sync.aligned.m16n8k16.row.col.f32.f16.f16.f32 "
        "{%0,%1,%2,%3}, {%4,%5,%6,%7}, {%8,%9}, {%0,%1,%2,%3};"
        : "+f"(c[0]), "+f"(c[1]), "+f"(c[2]), "+f"(c[3])
        : "r"(a[0]), "r"(a[1]), "r"(a[2]), "r"(a[3]), "r"(b[0]), "r"(b[1]));
}

// smem tile geometry (both GEMMs): 128 rows x 64 halfs (128 B) + 16 B pad
#define ROW_B   144
#define ARR_SZ  (128 * ROW_B)        // 18432
#define STG_SZ  (2 * ARR_SZ)         // 36864 per stage (2 arrays)
#define OFF_0   0
#define OFF_1   ARR_SZ
#define NSTG    3
#define SMEM_GEMM (NSTG * STG_SZ)    // 110592 -> 2 CTAs/SM

// lnproj dynamic smem layout (bytes)
#define LP_YS    0                   // ysm: 32 rows x 264 halfs (528 B)
#define LP_W     16896               // Wsm: 256 k-rows x 72 halfs (144 B)
#define LP_XS    (16896 + 36864)     // xs fp32 32x256 (32 KB); tbuf overlays
#define LP_SMEM  (LP_XS + 32768)     // 86528

// ---------------------------------------------------------------------------
// prep: blocks 0-255 rnorm; 256-383 W transpose; 384-391 proj-weight pack
// ---------------------------------------------------------------------------
__global__ __launch_bounds__(256) void k_prep(
    const float* __restrict__ mask, const float* __restrict__ wout,
    const float* __restrict__ w1,  const float* __restrict__ w2)
{
    if (blockIdx.x < 256) {
        const int i = blockIdx.x;
        const int j = threadIdx.x;
        __shared__ float colI[S_DIM];
        colI[j] = mask[j * N_DIM + i];
        __syncthreads();
        float acc = 0.0f;
#pragma unroll 8
        for (int s = 0; s < S_DIM; s++) acc += colI[s] * mask[s * N_DIM + j];
        g_rnorm[i * N_DIM + j] = 1.0f / (acc + 1e-3f);
    } else if (blockIdx.x < 384) {
        const int z = blockIdx.x - 256;
        for (int k = threadIdx.x; k < 1024; k += 256)
            g_W[z * 1024 + k] = __float2half(wout[(size_t)k * CZ + z]);
    } else {
        const int base = (blockIdx.x - 384) * 2048;
        for (int idx = threadIdx.x; idx < 2048; idx += 256) {
            const int e = base + idx;
            const int k = e >> 6;
            const int c = e & 63;
            const float v = (c < CH) ? w1[k * CH + c] : w2[k * CH + (c - CH)];
            g_Wp[e] = __float2half(v);
        }
    }
}

// ---------------------------------------------------------------------------
// LN + HMMA dual projection.
// grid = (n=256, sg=8); 256 thr; rows s = sg*32..+32 at fixed n; 8 warps.
// ---------------------------------------------------------------------------
__global__ __launch_bounds__(256) void k_lnproj(
    const float* __restrict__ m, const float* __restrict__ mask,
    const float* __restrict__ lnw, const float* __restrict__ lnb,
    const float* __restrict__ b1, const float* __restrict__ b2)
{
    extern __shared__ char smraw[];
    __half* ys   = (__half*)(smraw + LP_YS);     // [r][264]
    __half* Wsm  = (__half*)(smraw + LP_W);      // [k][72]
    float*  xs   = (float*)(smraw + LP_XS);      // [r][256]
    __half* tbuf = (__half*)(smraw + LP_XS);     // overlay: [cc][40]
    __shared__ float mu_s[32], inv_s[32], msm[32];

    const uint32_t ys_b  = smem_u32(ys);
    const uint32_t W_b   = smem_u32(Wsm);
    const int tid  = threadIdx.x;
    const int lane = tid & 31;
    const int wid  = tid >> 5;
    const int n    = blockIdx.x;
    const int sg   = blockIdx.y;

    const float wln = lnw[tid];
    const float bln = lnb[tid];

    // Phase A: load 32 rows of m (coalesced float4) + W smem (fp16) + mask
#pragma unroll
    for (int l = 0; l < 8; l++) {
        const int idx = tid + 256 * l;
        const int r   = idx >> 6;
        const int c4  = idx & 63;
        const size_t row = (size_t)((sg * 32 + r) * N_DIM + n);
        ((float4*)xs)[r * 64 + c4] = ((const float4*)(m + row * CM))[c4];
    }
#pragma unroll
    for (int l = 0; l < 8; l++) {
        const int idx = tid + 256 * l;          // 2048 uint4
        const int k   = idx >> 3;
        const int seg = idx & 7;
        *(uint4*)(Wsm + k * 72 + seg * 8) = *(const uint4*)(g_Wp + k * 64 + seg * 8);
    }
    if (tid < 32) msm[tid] = mask[(size_t)((sg * 32 + tid) * N_DIM + n)];
    __syncthreads();

    // Phase B: LN stats, warp w handles rows 4w..4w+3
#pragma unroll
    for (int rr = 0; rr < 4; rr++) {
        const int r = wid * 4 + rr;
        float s1 = 0.f, s2 = 0.f;
#pragma unroll
        for (int q = 0; q < 8; q++) {
            const float x = xs[r * 256 + lane + 32 * q];
            s1 += x; s2 += x * x;
        }
#pragma unroll
        for (int off = 16; off; off >>= 1) {
            s1 += __shfl_xor_sync(0xffffffffu, s1, off);
            s2 += __shfl_xor_sync(0xffffffffu, s2, off);
        }
        if (lane == 0) {
            const float mean = s1 * (1.0f / CM);
            const float var  = s2 * (1.0f / CM) - mean * mean;
            mu_s[r]  = mean;
            inv_s[r] = rsqrtf(var + 1e-5f);
        }
    }
    __syncthreads();

    // Phase C: normalize -> fp16 ysm
#pragma unroll 4
    for (int r = 0; r < 32; r++) {
        const float x = xs[r * 256 + tid];
        ys[r * 264 + tid] = __float2half((x - mu_s[r]) * inv_s[r] * wln + bln);
    }
    __syncthreads();

    // Phase D: HMMA projection. acc = 32 rows x 8 cols per warp.
    const int ar = lane & 15;
    const int ak = (lane >> 4) * 16;
    float acc[2][4];
#pragma unroll
    for (int t = 0; t < 2; t++)
#pragma unroll
        for (int q = 0; q < 4; q++) acc[t][q] = 0.f;

#pragma unroll
    for (int q2 = 0; q2 < 8; q2++) {               // k32 per iter
        uint32_t bf[4];
        ldm4t(bf, W_b + (uint32_t)(q2 * 32 + lane) * 144 + wid * 16);
#pragma unroll
        for (int s = 0; s < 2; s++) {              // kstep = 2*q2+s
            const int q = 2 * q2 + s;
            uint32_t af[2][4];
#pragma unroll
            for (int t = 0; t < 2; t++)
                ldm4(af[t], ys_b + (uint32_t)(t * 16 + ar) * 528 + q * 32 + ak);
            mma_fp16(acc[0], af[0], &bf[s * 2]);
            mma_fp16(acc[1], af[1], &bf[s * 2]);
        }
    }

    // Phase E: bias + mask -> tbuf[cc][r] fp16 (xs now dead)
    const int cc0 = wid * 8 + (lane & 3) * 2;
    const float bia0 = (cc0 < CH) ? b1[cc0] : b2[cc0 - CH];
    const float bia1 = (cc0 + 1 < CH) ? b1[cc0 + 1] : b2[cc0 + 1 - CH];
#pragma unroll
    for (int t = 0; t < 2; t++) {
#pragma unroll
        for (int q = 0; q < 4; q++) {
            const int r  = t * 16 + (lane >> 2) + (q >> 1) * 8;
            const int cc = cc0 + (q & 1);
            const float v = (acc[t][q] + ((q & 1) ? bia1 : bia0)) * msm[r];
            tbuf[cc * 40 + r] = __float2half(v);
        }
    }
    __syncthreads();

    // Phase F: coalesced K-major stores (64 B per output column)
    {
        const int cc  = tid >> 2;
        const int seg = tid & 3;
        uint4 v = *(const uint4*)(tbuf + cc * 40 + seg * 8);
        __half* dst = (cc < CH)
            ? (g_A + (size_t)(n * CH + cc) * S_DIM + sg * 32 + seg * 8)
            : (g_B + (size_t)(n * CH + (cc - CH)) * S_DIM + sg * 32 + seg * 8);
        *(uint4*)dst = v;
    }
}

// ---------------------------------------------------------------------------
// K2: C = A B^T, 1-pass HMMA. 128 threads, 4 warps 2x2, warp tile 64x64.
// CTA tile 128x128, K=256 in 4 chunks of 64, 3-stage ring.
// ---------------------------------------------------------------------------
__global__ __launch_bounds__(128, 2) void k_gemm1() {
    extern __shared__ char smraw[];
    const uint32_t sm0 = smem_u32(smraw);
    const int tid  = threadIdx.x;
    const int wid  = tid >> 5;
    const int lane = tid & 31;
    const int m0 = blockIdx.y * 128;
    const int n0 = blockIdx.x * 128;
    const int wm0 = (wid & 1) * 64;
    const int wn0 = (wid >> 1) * 64;

    const int ar = lane & 15;
    const int ak = (lane >> 4) * 16;
    const int br = (lane & 7) + ((lane >> 4) << 3);
    const int bk = ((lane >> 3) & 1) * 16;
    const uint32_t aoff = (uint32_t)(wm0 + ar) * ROW_B + ak;
    const uint32_t boff = (uint32_t)(wn0 + br) * ROW_B + bk;

    float acc[4][8][4];
#pragma unroll
    for (int t = 0; t < 4; t++)
#pragma unroll
        for (int j = 0; j < 8; j++)
#pragma unroll
            for (int q = 0; q < 4; q++) acc[t][j][q] = 0.f;

    auto stage = [&](int kc, uint32_t sbuf) {
#pragma unroll
        for (int l = 0; l < 8; l++) {
            const int idx = tid + 128 * l;      // 1024: row(128) x seg(8)
            const int row = idx >> 3;
            const int seg = idx & 7;
            const uint32_t d = sbuf + row * ROW_B + seg * 16;
            const size_t sa = (size_t)(m0 + row) * S_DIM + kc * 64 + seg * 8;
            const size_t sb = (size_t)(n0 + row) * S_DIM + kc * 64 + seg * 8;
            cp16(d + OFF_0, g_A + sa);
            cp16(d + OFF_1, g_B + sb);
        }
        CP_COMMIT();
    };

    stage(0, sm0);
    stage(1, sm0 + STG_SZ);
    stage(2, sm0 + 2 * STG_SZ);

#pragma unroll
    for (int kc = 0; kc < 4; kc++) {
        if (kc <= 1)      { CP_WAIT(2); }
        else if (kc == 2) { CP_WAIT(1); }
        else              { CP_WAIT(0); }
        __syncthreads();
        const uint32_t sbuf = sm0 + (kc % 3) * STG_SZ;
#pragma unroll
        for (int ks = 0; ks < 4; ks++) {
            uint32_t a[4][4], b[4][4];
#pragma unroll
            for (int t = 0; t < 4; t++)
                ldm4(a[t], sbuf + aoff + t * (16 * ROW_B) + ks * 32 + OFF_0);
#pragma unroll
            for (int p = 0; p < 4; p++)
                ldm4(b[p], sbuf + boff + p * (16 * ROW_B) + ks * 32 + OFF_1);
#pragma unroll
            for (int t = 0; t < 4; t++) {
#pragma unroll
                for (int j = 0; j < 8; j++)
                    mma_fp16(acc[t][j], a[t], &b[j >> 1][(j & 1) * 2]);
            }
        }
        __syncthreads();
        if (kc + 3 < 4) stage(kc + 3, sbuf);
    }

    // epilogue: plain fp16 C, packed u32 stores (row-major)
#pragma unroll
    for (int t = 0; t < 4; t++) {
        const int mg = m0 + wm0 + t * 16 + (lane >> 2);
#pragma unroll
        for (int j = 0; j < 8; j++) {
            const int nn = n0 + wn0 + j * 8 + (lane & 3) * 2;
            const float* cc = acc[t][j];
#pragma unroll
            for (int h = 0; h < 2; h++) {
                __half2 hp;
                hp.x = __float2half(cc[h * 2 + 0]);
                hp.y = __float2half(cc[h * 2 + 1]);
                const size_t o = (size_t)(mg + h * 8) * NH + nn;
                *(uint32_t*)(g_C + o) = *(uint32_t*)&hp;
            }
        }
    }
}

// ---------------------------------------------------------------------------
// K3: out[(i,j),z] = (sum_ce C[(i,c),(j,e)] W[ce,z] + b[z]) * rnorm[i,j]
// 128 threads, 4 warps 2x2, warp tile 64(j)x64(z). grid = 512 (i desc, jh).
// K=1024 in 16 chunks of 64, 3-stage ring.
// ---------------------------------------------------------------------------
__global__ __launch_bounds__(128, 2) void k_gemm2(
    const float* __restrict__ bout, float* __restrict__ out)
{
    extern __shared__ char smraw[];
    const uint32_t sm0 = smem_u32(smraw);
    const int tid  = threadIdx.x;
    const int wid  = tid >> 5;
    const int lane = tid & 31;
    const int i  = 255 - (blockIdx.x >> 1);
    const int jh = blockIdx.x & 1;
    const int wm0 = (wid & 1) * 64;      // j within tile
    const int wn0 = (wid >> 1) * 64;     // z

    const int ar = lane & 15;
    const int ak = (lane >> 4) * 16;
    const int br = (lane & 7) + ((lane >> 4) << 3);
    const int bk = ((lane >> 3) & 1) * 16;
    const uint32_t aoff = (uint32_t)(wm0 + ar) * ROW_B + ak;
    const uint32_t boff = (uint32_t)(wn0 + br) * ROW_B + bk;

    float acc[4][8][4];
#pragma unroll
    for (int t = 0; t < 4; t++)
#pragma unroll
        for (int j = 0; j < 8; j++)
#pragma unroll
            for (int q = 0; q < 4; q++) acc[t][j][q] = 0.f;

    auto stage = [&](int kc, uint32_t sbuf) {
#pragma unroll
        for (int l = 0; l < 8; l++) {
            const int idx = tid + 128 * l;
            const int row = idx >> 3;            // j-row (C) / z-row (W)
            const int seg = idx & 7;             // k-halfs seg*8..+8
            const uint32_t d = sbuf + row * ROW_B + seg * 16;
            const size_t sc = (size_t)(i * 32 + kc * 2 + (seg >> 2)) * NH +
                              (size_t)(jh * 128 + row) * 32 + (seg & 3) * 8;
            const size_t sw = (size_t)row * 1024 + kc * 64 + seg * 8;
            cp16(d + OFF_0, g_C + sc);
            cp16(d + OFF_1, g_W + sw);
        }
        CP_COMMIT();
    };

    stage(0, sm0);
    stage(1, sm0 + STG_SZ);
    stage(2, sm0 + 2 * STG_SZ);

    for (int kc = 0; kc < 16; kc++) {
        if (kc < 14)       { CP_WAIT(2); }
        else if (kc == 14) { CP_WAIT(1); }
        else               { CP_WAIT(0); }
        __syncthreads();
        const uint32_t sbuf = sm0 + (kc % 3) * STG_SZ;
#pragma unroll
        for (int ks = 0; ks < 4; ks++) {
            uint32_t a[4][4], b[4][4];
#pragma unroll
            for (int t = 0; t < 4; t++)
                ldm4(a[t], sbuf + aoff + t * (16 * ROW_B) + ks * 32 + OFF_0);
#pragma unroll
            for (int p = 0; p < 4; p++)
                ldm4(b[p], sbuf + boff + p * (16 * ROW_B) + ks * 32 + OFF_1);
#pragma unroll
            for (int t = 0; t < 4; t++) {
#pragma unroll
                for (int j = 0; j < 8; j++)
                    mma_fp16(acc[t][j], a[t], &b[j >> 1][(j & 1) * 2]);
            }
        }
        __syncthreads();
        if (kc + 3 < 16) stage(kc + 3, sbuf);
    }

    // epilogue: + bias, * rnorm, fp32 stores
#pragma unroll
    for (int t = 0; t < 4; t++) {
        const int jg = jh * 128 + wm0 + t * 16 + (lane >> 2);
        const float rn0 = g_rnorm[i * N_DIM + jg];
        const float rn1 = g_rnorm[i * N_DIM + jg + 8];
#pragma unroll
        for (int j = 0; j < 8; j++) {
            const int z = wn0 + j * 8 + (lane & 3) * 2;
            const float2 bz = *(const float2*)(bout + z);
            const float* cc = acc[t][j];
            float2 o0, o1;
            o0.x = (cc[0] + bz.x) * rn0;  o0.y = (cc[1] + bz.y) * rn0;
            o1.x = (cc[2] + bz.x) * rn1;  o1.y = (cc[3] + bz.y) * rn1;
            *(float2*)(out + (size_t)(i * N_DIM + jg) * CZ + z)     = o0;
            *(float2*)(out + (size_t)(i * N_DIM + jg + 8) * CZ + z) = o1;
        }
    }
}

// ---------------------------------------------------------------------------
extern "C" void kernel_launch(void* const* d_in, const int* in_sizes, int n_in,
                              void* d_out, int out_size)
{
    (void)in_sizes; (void)n_in; (void)out_size;
    const float* m    = (const float*)d_in[0];
    const float* mask = (const float*)d_in[1];
    const float* lnw  = (const float*)d_in[2];
    const float* lnb  = (const float*)d_in[3];
    const float* w1   = (const float*)d_in[4];
    const float* b1   = (const float*)d_in[5];
    const float* w2   = (const float*)d_in[6];
    const float* b2   = (const float*)d_in[7];
    const float* wout = (const float*)d_in[8];
    const float* bout = (const float*)d_in[9];
    float* out = (float*)d_out;

    cudaFuncSetAttribute((const void*)k_lnproj,
                         cudaFuncAttributeMaxDynamicSharedMemorySize, LP_SMEM);
    cudaFuncSetAttribute((const void*)k_gemm1,
                         cudaFuncAttributeMaxDynamicSharedMemorySize, SMEM_GEMM);
    cudaFuncSetAttribute((const void*)k_gemm2,
                         cudaFuncAttributeMaxDynamicSharedMemorySize, SMEM_GEMM);

    k_prep<<<392, 256>>>(mask, wout, w1, w2);
    k_lnproj<<<dim3(N_DIM, 8), 256, LP_SMEM>>>(m, mask, lnw, lnb, b1, b2);
    k_gemm1<<<dim3(NH / 128, NH / 128), 128, SMEM_GEMM>>>();
    k_gemm2<<<512, 128, SMEM_GEMM>>>(bout, out);
}